// round 8
// baseline (speedup 1.0000x reference)
#include <cuda_runtime.h>
#include <cstdint>

// GraphPool: out[s,a,f] = (deg(s,a)>0) * max over {a} ∪ {e in edges[s,a,:], e>=0} of atoms[s,e,f]
// S=512, A=128, F=128, D=6.
//
// NOTE: harness downcasts the reference's int64 edges to int32 (metadata dtype
// set is {float32, int32, bfloat16}). Edges are read as const int*.
//
// One CTA per s. atoms[s] tile (64KB) staged in dynamic SMEM; edges staged in
// SMEM. 256 threads: lane = float4 chunk of F (32 chunks), warp strides over A
// rows. All gathers are SMEM LDS.128, conflict-free (each lane a distinct 16B
// chunk); edge indices warp-uniform (broadcast, uniform predicate).

#define S_DIM 512
#define A_DIM 128
#define F_DIM 128
#define D_DIM 6
#define F4    (F_DIM / 4)          // 32 float4 per row
#define TILE_F4 (A_DIM * F4)       // 4096 float4 = 64KB
#define NEDGE (A_DIM * D_DIM)      // 768
#define SMEM_BYTES (TILE_F4 * 16 + NEDGE * 4)  // 65536 + 3072 = 68608

__global__ __launch_bounds__(256, 3)
void graphpool_kernel(const float* __restrict__ atoms,
                      const int* __restrict__ edges,
                      float* __restrict__ out) {
    extern __shared__ float smem_raw[];
    float4* tile = reinterpret_cast<float4*>(smem_raw);
    int*    esm  = reinterpret_cast<int*>(smem_raw + A_DIM * F_DIM);

    const int s   = blockIdx.x;
    const int tid = threadIdx.x;

    // Stage atoms[s] tile: 4096 float4, 256 threads x 16, fully coalesced.
    const float4* gtile = reinterpret_cast<const float4*>(atoms) + (size_t)s * TILE_F4;
#pragma unroll
    for (int i = 0; i < TILE_F4 / 256; i++) {
        tile[tid + i * 256] = gtile[tid + i * 256];
    }

    // Stage edges[s] (int32): 768 elements, coalesced.
    const int* ge = edges + (size_t)s * NEDGE;
    if (tid < NEDGE - 512) esm[tid + 512] = ge[tid + 512];
    esm[tid]       = ge[tid];
    esm[tid + 256] = ge[tid + 256];
    __syncthreads();

    const int lane = tid & 31;   // float4 chunk within F
    const int warp = tid >> 5;   // 8 warps stride over A

    float4* gout = reinterpret_cast<float4*>(out) + (size_t)s * TILE_F4;

#pragma unroll 4
    for (int a = warp; a < A_DIM; a += 8) {
        float4 v = tile[a * F4 + lane];   // self (always included)
        int deg = 0;
#pragma unroll
        for (int d = 0; d < D_DIM; d++) {
            const int e = esm[a * D_DIM + d];   // warp-uniform broadcast
            if (e >= 0) {
                deg++;
                const float4 n = tile[e * F4 + lane];
                v.x = fmaxf(v.x, n.x);
                v.y = fmaxf(v.y, n.y);
                v.z = fmaxf(v.z, n.z);
                v.w = fmaxf(v.w, n.w);
            }
        }
        if (deg == 0) { v.x = 0.f; v.y = 0.f; v.z = 0.f; v.w = 0.f; }
        gout[a * F4 + lane] = v;   // coalesced 512B per warp per row
    }
}

extern "C" void kernel_launch(void* const* d_in, const int* in_sizes, int n_in,
                              void* d_out, int out_size) {
    const float* atoms = (const float*)d_in[0];
    const int*   edges = (const int*)d_in[1];
    float*       out   = (float*)d_out;

    // Idempotent attribute set; safe under graph capture.
    cudaFuncSetAttribute(graphpool_kernel,
                         cudaFuncAttributeMaxDynamicSharedMemorySize, SMEM_BYTES);

    graphpool_kernel<<<S_DIM, 256, SMEM_BYTES>>>(atoms, edges, out);
}

// round 9
// speedup vs baseline: 1.0135x; 1.0135x over previous
#include <cuda_runtime.h>
#include <cstdint>

// GraphPool: out[s,a,f] = (deg(s,a)>0) * max over {a} ∪ {e in edges[s,a,:], e>=0} of atoms[s,e,f]
// S=512, A=128, F=128, D=6.  Edges arrive as int32 (harness downcasts int64).
//
// One CTA per s. atoms[s] tile (64KB) + edges (3KB) in dynamic SMEM.
// R8 ran 256 thr/CTA -> 24 warps/SM (occ 31%, issue 30%): latency-bound, smem
// crossbar only 55%. This version: 512 thr/CTA, same 3 CTAs/SM (smem-limited)
// -> 48 warps/SM. launch_bounds(512,3) caps regs at 42 to avoid regfile limit.

#define S_DIM 512
#define A_DIM 128
#define F_DIM 128
#define D_DIM 6
#define F4      (F_DIM / 4)            // 32 float4 per row
#define TILE_F4 (A_DIM * F4)           // 4096 float4 = 64KB
#define NEDGE   (A_DIM * D_DIM)        // 768
#define SMEM_BYTES (TILE_F4 * 16 + NEDGE * 4)   // 68608
#define NTHR 512
#define NWARP (NTHR / 32)              // 16 warps; each handles 8 rows

__global__ __launch_bounds__(NTHR, 3)
void graphpool_kernel(const float* __restrict__ atoms,
                      const int* __restrict__ edges,
                      float* __restrict__ out) {
    extern __shared__ float smem_raw[];
    float4* tile = reinterpret_cast<float4*>(smem_raw);
    int*    esm  = reinterpret_cast<int*>(smem_raw + A_DIM * F_DIM);

    const int s   = blockIdx.x;
    const int tid = threadIdx.x;

    // Stage atoms[s]: 4096 float4, 8 per thread, fully coalesced.
    const float4* gtile = reinterpret_cast<const float4*>(atoms) + (size_t)s * TILE_F4;
#pragma unroll
    for (int i = 0; i < TILE_F4 / NTHR; i++) {
        tile[tid + i * NTHR] = gtile[tid + i * NTHR];
    }

    // Stage edges[s]: 768 int32.
    const int* ge = edges + (size_t)s * NEDGE;
    esm[tid] = ge[tid];
    if (tid < NEDGE - NTHR) esm[tid + NTHR] = ge[tid + NTHR];
    __syncthreads();

    const int lane = tid & 31;   // float4 chunk within F
    const int warp = tid >> 5;   // 16 warps stride over A

    float4* gout = reinterpret_cast<float4*>(out) + (size_t)s * TILE_F4;

#pragma unroll 4
    for (int a = warp; a < A_DIM; a += NWARP) {
        float4 v = tile[a * F4 + lane];          // self (always included)
        int deg = 0;
#pragma unroll
        for (int d = 0; d < D_DIM; d++) {
            const int e = esm[a * D_DIM + d];    // warp-uniform broadcast
            if (e >= 0) {
                deg++;
                const float4 n = tile[e * F4 + lane];
                v.x = fmaxf(v.x, n.x);
                v.y = fmaxf(v.y, n.y);
                v.z = fmaxf(v.z, n.z);
                v.w = fmaxf(v.w, n.w);
            }
        }
        if (deg == 0) { v.x = 0.f; v.y = 0.f; v.z = 0.f; v.w = 0.f; }
        gout[a * F4 + lane] = v;                 // coalesced 512B per warp
    }
}

extern "C" void kernel_launch(void* const* d_in, const int* in_sizes, int n_in,
                              void* d_out, int out_size) {
    const float* atoms = (const float*)d_in[0];
    const int*   edges = (const int*)d_in[1];
    float*       out   = (float*)d_out;

    cudaFuncSetAttribute(graphpool_kernel,
                         cudaFuncAttributeMaxDynamicSharedMemorySize, SMEM_BYTES);

    graphpool_kernel<<<S_DIM, NTHR, SMEM_BYTES>>>(atoms, edges, out);
}

// round 10
// speedup vs baseline: 1.1364x; 1.1212x over previous
#include <cuda_runtime.h>
#include <cstdint>

// GraphPool: out[s,a,f] = (deg(s,a)>0) * max over {a} ∪ {e in edges[s,a,:], e>=0} of atoms[s,e,f]
// S=512, A=128, F=128, D=6.  Edges arrive as int32.
//
// One CTA per s. atoms[s] tile (64KB) brought in via cp.async.bulk (TMA bulk,
// no per-thread LDG/STS round trip); edges (3KB) staged as int2 while the TMA
// is in flight. Gather loop: per warp 8 rows, per row 3x LDS.64 (edge idx,
// broadcast) + up to 7x LDS.128 (row gather, conflict-free) + STG.128.

#define S_DIM 512
#define A_DIM 128
#define F_DIM 128
#define D_DIM 6
#define F4      (F_DIM / 4)            // 32 float4 per row
#define TILE_F4 (A_DIM * F4)           // 4096 float4 = 64KB
#define TILE_BYTES (TILE_F4 * 16)      // 65536
#define NEDGE   (A_DIM * D_DIM)        // 768 ints = 384 int2
#define NTHR 512
#define NWARP (NTHR / 32)              // 16 warps, 8 rows each

// smem layout: [0:8) mbarrier | [8:3080) edges (768 int) pad to 128 | tile
#define SM_EDGE_OFF 128                 // bytes; 8B-aligned rows inside
#define SM_TILE_OFF (SM_EDGE_OFF + 3072)       // 3200 -> pad to 3328? keep 16B align
#define SMEM_BYTES  (SM_TILE_OFF + TILE_BYTES) // 3200+65536 = 68736

__device__ __forceinline__ uint32_t smem_u32(const void* p) {
    uint32_t a;
    asm("{ .reg .u64 t; cvta.to.shared.u64 t, %1; cvt.u32.u64 %0, t; }" : "=r"(a) : "l"(p));
    return a;
}

__global__ __launch_bounds__(NTHR, 3)
void graphpool_kernel(const float* __restrict__ atoms,
                      const int* __restrict__ edges,
                      float* __restrict__ out) {
    extern __shared__ __align__(128) char smem[];
    uint32_t smem_base = smem_u32(smem);
    int*    esm  = reinterpret_cast<int*>(smem + SM_EDGE_OFF);
    float4* tile = reinterpret_cast<float4*>(smem + SM_TILE_OFF);

    const int s   = blockIdx.x;
    const int tid = threadIdx.x;
    const uint32_t mbar = smem_base;                 // offset 0
    const uint32_t tile_sm = smem_base + SM_TILE_OFF;

    if (tid == 0) {
        asm volatile("mbarrier.init.shared.b64 [%0], 1;" :: "r"(mbar) : "memory");
    }
    __syncthreads();   // init visible to all before wait / TMA use

    if (tid == 0) {
        asm volatile("fence.proxy.async.shared::cta;" ::: "memory");
        asm volatile("mbarrier.arrive.expect_tx.shared.b64 _, [%0], %1;"
                     :: "r"(mbar), "r"((uint32_t)TILE_BYTES) : "memory");
        const float* src = atoms + (size_t)s * (A_DIM * F_DIM);
        asm volatile(
            "cp.async.bulk.shared::cta.global.mbarrier::complete_tx::bytes "
            "[%0], [%1], %2, [%3];"
            :: "r"(tile_sm), "l"(src), "r"((uint32_t)TILE_BYTES), "r"(mbar)
            : "memory");
    }

    // Stage edges (int2) while the bulk copy is in flight.
    {
        const int2* ge2 = reinterpret_cast<const int2*>(edges + (size_t)s * NEDGE);
        int2* es2 = reinterpret_cast<int2*>(esm);
        if (tid < NEDGE / 2) es2[tid] = ge2[tid];
    }
    __syncthreads();   // edges visible

    // Wait for the tile (phase 0), acquire ordering for subsequent LDS.
    {
        uint32_t done;
        asm volatile(
            "{\n\t.reg .pred p;\n\t"
            "mbarrier.try_wait.parity.acquire.cta.shared::cta.b64 p, [%1], 0;\n\t"
            "selp.b32 %0, 1, 0, p;\n\t}"
            : "=r"(done) : "r"(mbar) : "memory");
        if (!done) {
            asm volatile(
                "{\n\t.reg .pred P1;\n\t"
                "WL_%=:\n\t"
                "mbarrier.try_wait.parity.acquire.cta.shared::cta.b64 P1, [%0], 0, 0x989680;\n\t"
                "@P1 bra.uni WD_%=;\n\t"
                "bra.uni WL_%=;\n\t"
                "WD_%=:\n\t}"
                :: "r"(mbar) : "memory");
        }
    }

    const int lane = tid & 31;
    const int warp = tid >> 5;

    float4* gout = reinterpret_cast<float4*>(out) + (size_t)s * TILE_F4;

#pragma unroll 4
    for (int a = warp; a < A_DIM; a += NWARP) {
        const int2* ep = reinterpret_cast<const int2*>(&esm[a * D_DIM]); // 24B rows, 8B aligned
        const int2 e01 = ep[0];
        const int2 e23 = ep[1];
        const int2 e45 = ep[2];
        const int e[D_DIM] = { e01.x, e01.y, e23.x, e23.y, e45.x, e45.y };

        float4 v = tile[a * F4 + lane];          // self (always included)
        int deg = 0;
#pragma unroll
        for (int d = 0; d < D_DIM; d++) {
            if (e[d] >= 0) {
                deg++;
                const float4 n = tile[e[d] * F4 + lane];
                v.x = fmaxf(v.x, n.x);
                v.y = fmaxf(v.y, n.y);
                v.z = fmaxf(v.z, n.z);
                v.w = fmaxf(v.w, n.w);
            }
        }
        if (deg == 0) { v.x = 0.f; v.y = 0.f; v.z = 0.f; v.w = 0.f; }
        gout[a * F4 + lane] = v;                 // coalesced 512B per warp
    }
}

extern "C" void kernel_launch(void* const* d_in, const int* in_sizes, int n_in,
                              void* d_out, int out_size) {
    const float* atoms = (const float*)d_in[0];
    const int*   edges = (const int*)d_in[1];
    float*       out   = (float*)d_out;

    cudaFuncSetAttribute(graphpool_kernel,
                         cudaFuncAttributeMaxDynamicSharedMemorySize, SMEM_BYTES);

    graphpool_kernel<<<S_DIM, NTHR, SMEM_BYTES>>>(atoms, edges, out);
}